// round 1
// baseline (speedup 1.0000x reference)
#include <cuda_runtime.h>
#include <math.h>

#define BATCH   8
#define TLEN    2048
#define NCH     512
#define M_TOTAL (BATCH * TLEN)   // 16384
#define CHUNK   256
#define NCHUNK  (TLEN / CHUNK)   // 8

// ---------------- scratch (device globals; no dynamic allocation) ----------
__device__ float g_vr[M_TOTAL * NCH];   // 32 MB
__device__ float g_vi[M_TOTAL * NCH];   // 32 MB
__device__ float g_xr[M_TOTAL * NCH];   // 32 MB
__device__ float g_xi[M_TOTAL * NCH];   // 32 MB
__device__ float g_cr[BATCH * NCHUNK * NCH];
__device__ float g_ci[BATCH * NCHUNK * NCH];
__device__ float g_hr[BATCH * NCHUNK * NCH];
__device__ float g_hi[BATCH * NCHUNK * NCH];

// ---------------------------------------------------------------------------
// GEMM1: [vr | vi] = u @ (diag(gamma) * [Br | Bi])
//   A = u  (M_TOTAL x 512, row-major)
//   Bcat (512 x 1024): cols [0,512) from Br, [512,1024) from Bi, rows scaled by gamma[k]
// 128x128 tile, BK=8, 256 threads, 8x8 micro-tile (split 4+4 for conflict-free LDS.128)
// ---------------------------------------------------------------------------
__global__ __launch_bounds__(256) void gemm1_kernel(
    const float* __restrict__ u, const float* __restrict__ Br,
    const float* __restrict__ Bi, const float* __restrict__ gamma)
{
    __shared__ float As[8][132];   // padded, stored transposed: As[k][m]
    __shared__ float Bs[8][128];

    const int tid = threadIdx.x;
    const int tx = tid & 15;        // 0..15
    const int ty = tid >> 4;        // 0..15
    const int row0 = blockIdx.y * 128;
    const int col0 = blockIdx.x * 128;          // 0..1023
    const int is_im = (blockIdx.x >= 4);
    const float* __restrict__ Bsrc = is_im ? Bi : Br;
    const int bcol = col0 - (is_im ? 512 : 0);  // column within the 512-wide plane

    // A tile load: one float4 per thread. 128 rows x 8 cols.
    const int a_r = tid >> 1;          // 0..127
    const int a_c = (tid & 1) * 4;     // 0 or 4
    // B tile load: one float4 per thread. 8 rows x 128 cols.
    const int b_r = tid >> 5;          // 0..7
    const int b_c = (tid & 31) * 4;    // 0..124

    float acc[8][8];
#pragma unroll
    for (int i = 0; i < 8; i++)
#pragma unroll
        for (int j = 0; j < 8; j++) acc[i][j] = 0.f;

    for (int kt = 0; kt < 512; kt += 8) {
        float4 av = *(const float4*)&u[(size_t)(row0 + a_r) * NCH + kt + a_c];
        float g = gamma[kt + b_r];
        float4 bv = *(const float4*)&Bsrc[(size_t)(kt + b_r) * NCH + bcol + b_c];
        bv.x *= g; bv.y *= g; bv.z *= g; bv.w *= g;

        __syncthreads();   // previous iteration's compute done
        As[a_c + 0][a_r] = av.x;
        As[a_c + 1][a_r] = av.y;
        As[a_c + 2][a_r] = av.z;
        As[a_c + 3][a_r] = av.w;
        *(float4*)&Bs[b_r][b_c] = bv;
        __syncthreads();

#pragma unroll
        for (int k = 0; k < 8; k++) {
            float a[8], b[8];
            *(float4*)&a[0] = *(const float4*)&As[k][ty * 4];
            *(float4*)&a[4] = *(const float4*)&As[k][64 + ty * 4];
            *(float4*)&b[0] = *(const float4*)&Bs[k][tx * 4];
            *(float4*)&b[4] = *(const float4*)&Bs[k][64 + tx * 4];
#pragma unroll
            for (int i = 0; i < 8; i++)
#pragma unroll
                for (int j = 0; j < 8; j++) acc[i][j] = fmaf(a[i], b[j], acc[i][j]);
        }
    }

    float* __restrict__ dst = is_im ? g_vi : g_vr;
#pragma unroll
    for (int ih = 0; ih < 2; ih++)
#pragma unroll
        for (int i = 0; i < 4; i++) {
            int r = row0 + ih * 64 + ty * 4 + i;
#pragma unroll
            for (int jh = 0; jh < 2; jh++) {
                int c = bcol + jh * 64 + tx * 4;
                float4 o = make_float4(acc[ih * 4 + i][jh * 4 + 0], acc[ih * 4 + i][jh * 4 + 1],
                                       acc[ih * 4 + i][jh * 4 + 2], acc[ih * 4 + i][jh * 4 + 3]);
                *(float4*)&dst[(size_t)r * NCH + c] = o;
            }
        }
}

// ---------------------------------------------------------------------------
// GEMM2: y = [xr xi] @ [Cr ; -Ci] + D .* u
//   A (M_TOTAL x 1024): k<512 from g_xr, k>=512 from g_xi (each M x 512 planes)
//   B (1024 x 512): rows <512 = Cr, rows >=512 = -Ci
// ---------------------------------------------------------------------------
__global__ __launch_bounds__(256) void gemm2_kernel(
    const float* __restrict__ Cr, const float* __restrict__ Ci,
    const float* __restrict__ D, const float* __restrict__ u,
    float* __restrict__ y)
{
    __shared__ float As[8][132];
    __shared__ float Bs[8][128];

    const int tid = threadIdx.x;
    const int tx = tid & 15;
    const int ty = tid >> 4;
    const int row0 = blockIdx.y * 128;
    const int col0 = blockIdx.x * 128;    // 0..511

    const int a_r = tid >> 1;
    const int a_c = (tid & 1) * 4;
    const int b_r = tid >> 5;
    const int b_c = (tid & 31) * 4;

    float acc[8][8];
#pragma unroll
    for (int i = 0; i < 8; i++)
#pragma unroll
        for (int j = 0; j < 8; j++) acc[i][j] = 0.f;

    for (int kt = 0; kt < 1024; kt += 8) {
        const int upper = (kt >= 512);
        const float* __restrict__ Aplane = upper ? g_xi : g_xr;
        const int kk = kt - (upper ? 512 : 0);

        float4 av = *(const float4*)&Aplane[(size_t)(row0 + a_r) * NCH + kk + a_c];
        float4 bv;
        if (!upper) {
            bv = *(const float4*)&Cr[(size_t)(kt + b_r) * NCH + col0 + b_c];
        } else {
            bv = *(const float4*)&Ci[(size_t)(kk + b_r) * NCH + col0 + b_c];
            bv.x = -bv.x; bv.y = -bv.y; bv.z = -bv.z; bv.w = -bv.w;
        }

        __syncthreads();
        As[a_c + 0][a_r] = av.x;
        As[a_c + 1][a_r] = av.y;
        As[a_c + 2][a_r] = av.z;
        As[a_c + 3][a_r] = av.w;
        *(float4*)&Bs[b_r][b_c] = bv;
        __syncthreads();

#pragma unroll
        for (int k = 0; k < 8; k++) {
            float a[8], b[8];
            *(float4*)&a[0] = *(const float4*)&As[k][ty * 4];
            *(float4*)&a[4] = *(const float4*)&As[k][64 + ty * 4];
            *(float4*)&b[0] = *(const float4*)&Bs[k][tx * 4];
            *(float4*)&b[4] = *(const float4*)&Bs[k][64 + tx * 4];
#pragma unroll
            for (int i = 0; i < 8; i++)
#pragma unroll
                for (int j = 0; j < 8; j++) acc[i][j] = fmaf(a[i], b[j], acc[i][j]);
        }
    }

    // epilogue: + D[c] * u[r][c]
#pragma unroll
    for (int ih = 0; ih < 2; ih++)
#pragma unroll
        for (int i = 0; i < 4; i++) {
            int r = row0 + ih * 64 + ty * 4 + i;
#pragma unroll
            for (int jh = 0; jh < 2; jh++) {
                int c = col0 + jh * 64 + tx * 4;
                float4 dv = *(const float4*)&D[c];
                float4 uv = *(const float4*)&u[(size_t)r * NCH + c];
                float4 o = make_float4(
                    fmaf(dv.x, uv.x, acc[ih * 4 + i][jh * 4 + 0]),
                    fmaf(dv.y, uv.y, acc[ih * 4 + i][jh * 4 + 1]),
                    fmaf(dv.z, uv.z, acc[ih * 4 + i][jh * 4 + 2]),
                    fmaf(dv.w, uv.w, acc[ih * 4 + i][jh * 4 + 3]));
                *(float4*)&y[(size_t)r * NCH + c] = o;
            }
        }
}

// ---------------------------------------------------------------------------
// Scan: x_t = lam * x_{t-1} + v_t  (complex, per (batch, channel))
// Pass 1 (WRITE_X=false): per-chunk local scan from 0, record chunk carry.
// Pass 3 (WRITE_X=true):  replay with the correct incoming state, write x.
// ---------------------------------------------------------------------------
template <bool WRITE_X>
__global__ __launch_bounds__(128) void scan_chunk_kernel(
    const float* __restrict__ nu, const float* __restrict__ theta)
{
    const int n = blockIdx.x * 128 + threadIdx.x;   // channel
    const int c = blockIdx.y;                       // chunk
    const int b = blockIdx.z;                       // batch

    const float r = expf(-expf(nu[n]));
    const float lr = r * cosf(theta[n]);
    const float li = r * sinf(theta[n]);

    float xr, xi;
    if (WRITE_X) {
        const int idx = (b * NCHUNK + c) * NCH + n;
        xr = g_hr[idx]; xi = g_hi[idx];
    } else {
        xr = 0.f; xi = 0.f;
    }

    size_t base = ((size_t)(b * TLEN + c * CHUNK)) * NCH + n;
#pragma unroll 4
    for (int t = 0; t < CHUNK; t++) {
        const size_t off = base + (size_t)t * NCH;
        float vr = g_vr[off];
        float vi = g_vi[off];
        float nxr = fmaf(lr, xr, fmaf(-li, xi, vr));
        float nxi = fmaf(lr, xi, fmaf( li, xr, vi));
        xr = nxr; xi = nxi;
        if (WRITE_X) { g_xr[off] = xr; g_xi[off] = xi; }
    }
    if (!WRITE_X) {
        const int idx = (b * NCHUNK + c) * NCH + n;
        g_cr[idx] = xr; g_ci[idx] = xi;
    }
}

// Pass 2: combine chunk carries -> incoming state per chunk (h). Tiny.
__global__ __launch_bounds__(512) void scan_combine_kernel(
    const float* __restrict__ nu, const float* __restrict__ theta)
{
    const int b = blockIdx.x;
    const int n = threadIdx.x;

    const float r = expf(-expf(nu[n]));
    float Lr = r * cosf(theta[n]);
    float Li = r * sinf(theta[n]);
    // lam^CHUNK via repeated squaring (CHUNK = 256 = 2^8)
#pragma unroll
    for (int s = 0; s < 8; s++) {
        float nr = Lr * Lr - Li * Li;
        float ni = 2.f * Lr * Li;
        Lr = nr; Li = ni;
    }

    float hr = 0.f, hi = 0.f;
#pragma unroll
    for (int c = 0; c < NCHUNK; c++) {
        const int idx = (b * NCHUNK + c) * NCH + n;
        g_hr[idx] = hr; g_hi[idx] = hi;
        float cr = g_cr[idx], ci = g_ci[idx];
        float nhr = fmaf(Lr, hr, fmaf(-Li, hi, cr));
        float nhi = fmaf(Lr, hi, fmaf( Li, hr, ci));
        hr = nhr; hi = nhi;
    }
}

// ---------------------------------------------------------------------------
extern "C" void kernel_launch(void* const* d_in, const int* in_sizes, int n_in,
                              void* d_out, int out_size)
{
    const float* u     = (const float*)d_in[0];
    const float* C_re  = (const float*)d_in[1];
    const float* C_im  = (const float*)d_in[2];
    const float* B_re  = (const float*)d_in[3];
    const float* B_im  = (const float*)d_in[4];
    const float* D     = (const float*)d_in[5];
    const float* nu    = (const float*)d_in[6];
    const float* theta = (const float*)d_in[7];
    const float* gamma = (const float*)d_in[8];
    float* y = (float*)d_out;

    (void)in_sizes; (void)n_in; (void)out_size;

    // GEMM1: v = (gamma .* u) @ [Br | Bi]
    gemm1_kernel<<<dim3(8, M_TOTAL / 128), 256>>>(u, B_re, B_im, gamma);
    // Scan pass 1: chunk carries
    scan_chunk_kernel<false><<<dim3(NCH / 128, NCHUNK, BATCH), 128>>>(nu, theta);
    // Scan pass 2: combine carries across chunks
    scan_combine_kernel<<<BATCH, NCH>>>(nu, theta);
    // Scan pass 3: replay with correct incoming state, write x
    scan_chunk_kernel<true><<<dim3(NCH / 128, NCHUNK, BATCH), 128>>>(nu, theta);
    // GEMM2: y = Re(x @ C) + D .* u
    gemm2_kernel<<<dim3(NCH / 128, M_TOTAL / 128), 256>>>(C_re, C_im, D, u, y);
}